// round 1
// baseline (speedup 1.0000x reference)
#include <cuda_runtime.h>
#include <math.h>

constexpr int Bq = 64, Fq = 256, Tq = 1024, Hq = 1024, Oq = 512;
constexpr int NB_RNN = 128;

// Scratch (allocations are forbidden; __device__ globals are the sanctioned path)
__device__ float g_U[(size_t)Bq * Tq * Hq];   // (B, T, H) = x@Wx + b
__device__ float g_S[(size_t)Bq * Tq * Hq];   // (B, T, H) states
__device__ unsigned g_bar;

__global__ void reset_kernel() { g_bar = 0u; }

// ---------------------------------------------------------------------------
// Tiled fp32 GEMM with bias: C[M,N] = A*B + bias.  128x128 CTA tile, 8x8
// thread tile, K-tile 8.  MODE 0: A is x gathered as A[r][f] = x[b,f,t]
// with r = b*T + t (coalesced along t).  MODE 1: A row-major [M,K].
// ---------------------------------------------------------------------------
template <int MODE, int KDIM, int NDIM>
__global__ __launch_bounds__(256, 2) void gemm_bias_kernel(
    const float* __restrict__ A, const float* __restrict__ Bm,
    const float* __restrict__ bias, float* __restrict__ C) {
  __shared__ float sA[8][128];
  __shared__ float sB[8][128];
  const int tid = threadIdx.x;
  const int n0 = blockIdx.x * 128;
  const int m0 = blockIdx.y * 128;
  const int tx = tid & 15, ty = tid >> 4;
  const int ia = tid & 127, ja = tid >> 7;

  float acc[8][8];
#pragma unroll
  for (int i = 0; i < 8; i++)
#pragma unroll
    for (int j = 0; j < 8; j++) acc[i][j] = 0.0f;

  for (int k0 = 0; k0 < KDIM; k0 += 8) {
#pragma unroll
    for (int u = 0; u < 4; u++) {
      const int j = ja + u * 2;
      float v;
      if (MODE == 0) {
        const int r = m0 + ia;
        const int bb = r >> 10;       // T = 1024
        const int tt = r & 1023;
        v = A[(size_t)bb * (Fq * Tq) + (size_t)(k0 + j) * Tq + tt];
      } else {
        v = A[(size_t)(m0 + ia) * KDIM + (k0 + j)];
      }
      sA[j][ia] = v;
      sB[j][ia] = Bm[(size_t)(k0 + j) * NDIM + n0 + ia];
    }
    __syncthreads();
#pragma unroll
    for (int k = 0; k < 8; k++) {
      float a8[8], b8[8];
      *(float4*)&a8[0] = *(const float4*)&sA[k][ty * 8];
      *(float4*)&a8[4] = *(const float4*)&sA[k][ty * 8 + 4];
      *(float4*)&b8[0] = *(const float4*)&sB[k][tx * 8];
      *(float4*)&b8[4] = *(const float4*)&sB[k][tx * 8 + 4];
#pragma unroll
      for (int i = 0; i < 8; i++)
#pragma unroll
        for (int j = 0; j < 8; j++) acc[i][j] = fmaf(a8[i], b8[j], acc[i][j]);
    }
    __syncthreads();
  }

  float bv[8];
#pragma unroll
  for (int j = 0; j < 8; j++) bv[j] = bias[n0 + tx * 8 + j];
#pragma unroll
  for (int i = 0; i < 8; i++) {
    const size_t row = (size_t)(m0 + ty * 8 + i);
    float4 v0, v1;
    v0.x = acc[i][0] + bv[0]; v0.y = acc[i][1] + bv[1];
    v0.z = acc[i][2] + bv[2]; v0.w = acc[i][3] + bv[3];
    v1.x = acc[i][4] + bv[4]; v1.y = acc[i][5] + bv[5];
    v1.z = acc[i][6] + bv[6]; v1.w = acc[i][7] + bv[7];
    *(float4*)&C[row * NDIM + n0 + tx * 8] = v0;
    *(float4*)&C[row * NDIM + n0 + tx * 8 + 4] = v1;
  }
}

// ---------------------------------------------------------------------------
// Persistent recurrent kernel.  128 CTAs (co-resident), CTA owns columns
// [j0, j0+8) of the new state for all 64 batch rows.  Thread tid holds
// Wh[tid*4 .. tid*4+4][j0 .. j0+8) in registers (32 regs) -> each state
// float4 load feeds 32 FMAs, zero intra-CTA redundancy.  Warp-halving
// shuffle fold (9 shuffles) reduces 8 j-partials over 32 lanes; warps are
// combined through SMEM.  Grid-wide counter barrier between steps.
// ---------------------------------------------------------------------------
__global__ __launch_bounds__(256, 1) void rnn_kernel(const float* __restrict__ Wh) {
  __shared__ float sRed[8][64][8];  // [warp][b][j] 16 KB
  const int tid = threadIdx.x;
  const int lane = tid & 31, warp = tid >> 5;
  const int j0 = blockIdx.x * 8;
  const int klo = tid * 4;

  float wh[4][8];
#pragma unroll
  for (int i = 0; i < 4; i++)
#pragma unroll
    for (int j = 0; j < 8; j++)
      wh[i][j] = Wh[(size_t)(klo + i) * Hq + j0 + j];

  unsigned target = NB_RNN;
  auto gbarrier = [&]() {
    __syncthreads();
    if (tid == 0) {
      __threadfence();
      atomicAdd(&g_bar, 1u);
      while (*((volatile unsigned*)&g_bar) < target) {}
    }
    __syncthreads();
    target += NB_RNN;
  };

  // t = 0 : S0 = tanh(U0)   (initial state is zero)
#pragma unroll
  for (int u = 0; u < 2; u++) {
    const int idx = tid + u * 256;
    const int b = idx >> 3, j = idx & 7;
    const size_t off = (size_t)b * (Tq * Hq) + j0 + j;
    __stcg(&g_S[off], tanhf(__ldg(&g_U[off])));
  }

  for (int t = 1; t < Tq; t++) {
    gbarrier();  // S[t-1] fully written by all CTAs

    const float* Sp = g_S + (size_t)(t - 1) * Hq + klo;
    float4 s4 = __ldcg((const float4*)Sp);
    for (int b = 0; b < Bq; b++) {
      const float4 cur = s4;
      if (b + 1 < Bq) s4 = __ldcg((const float4*)(Sp + (size_t)(b + 1) * (Tq * Hq)));

      float acc[8];
#pragma unroll
      for (int j = 0; j < 8; j++)
        acc[j] = fmaf(cur.x, wh[0][j],
                 fmaf(cur.y, wh[1][j],
                 fmaf(cur.z, wh[2][j], cur.w * wh[3][j])));

      // warp fold: 8 accs over 32 lanes -> lane group holds j = (lane>>2)&7
      {
        const bool up = (lane & 16) != 0;
#pragma unroll
        for (int i = 0; i < 4; i++) {
          const float send = up ? acc[i] : acc[4 + i];
          const float rec = __shfl_xor_sync(0xffffffffu, send, 16);
          acc[i] = (up ? acc[4 + i] : acc[i]) + rec;
        }
      }
      {
        const bool up = (lane & 8) != 0;
#pragma unroll
        for (int i = 0; i < 2; i++) {
          const float send = up ? acc[i] : acc[2 + i];
          const float rec = __shfl_xor_sync(0xffffffffu, send, 8);
          acc[i] = (up ? acc[2 + i] : acc[i]) + rec;
        }
      }
      {
        const bool up = (lane & 4) != 0;
        const float send = up ? acc[0] : acc[1];
        const float rec = __shfl_xor_sync(0xffffffffu, send, 4);
        acc[0] = (up ? acc[1] : acc[0]) + rec;
      }
      acc[0] += __shfl_xor_sync(0xffffffffu, acc[0], 2);
      acc[0] += __shfl_xor_sync(0xffffffffu, acc[0], 1);
      if ((lane & 3) == 0) sRed[warp][b][(lane >> 2) & 7] = acc[0];
    }
    __syncthreads();

    // combine 8 warps, add U, tanh, store S[t]
#pragma unroll
    for (int u = 0; u < 2; u++) {
      const int idx = tid + u * 256;
      const int b = idx >> 3, j = idx & 7;
      float sum = sRed[0][b][j];
#pragma unroll
      for (int w = 1; w < 8; w++) sum += sRed[w][b][j];
      const size_t off = (size_t)b * (Tq * Hq) + (size_t)t * Hq + j0 + j;
      __stcg(&g_S[off], tanhf(__ldg(&g_U[off]) + sum));
    }
  }
}

extern "C" void kernel_launch(void* const* d_in, const int* in_sizes, int n_in,
                              void* d_out, int out_size) {
  const float* x    = (const float*)d_in[0];
  const float* Wx   = (const float*)d_in[1];
  const float* Wh   = (const float*)d_in[2];
  const float* bv   = (const float*)d_in[3];
  const float* Wout = (const float*)d_in[4];
  const float* bout = (const float*)d_in[5];
  float* out = (float*)d_out;

  float* U = nullptr;
  float* S = nullptr;
  cudaGetSymbolAddress((void**)&U, g_U);
  cudaGetSymbolAddress((void**)&S, g_S);

  reset_kernel<<<1, 1>>>();
  // Phase 1: U = x @ Wx + b   (M = B*T = 65536, K = 256, N = 1024)
  gemm_bias_kernel<0, Fq, Hq><<<dim3(Hq / 128, (Bq * Tq) / 128), 256>>>(x, Wx, bv, U);
  // Phase 2: sequential recurrence, persistent cooperative kernel
  rnn_kernel<<<NB_RNN, 256>>>(Wh);
  // Phase 3: out = states @ Wout + bout  (M = 65536, K = 1024, N = 512)
  gemm_bias_kernel<1, Hq, Oq><<<dim3(Oq / 128, (Bq * Tq) / 128), 256>>>(S, Wout, bout, out);
}

// round 2
// speedup vs baseline: 1.7621x; 1.7621x over previous
#include <cuda_runtime.h>
#include <math.h>

constexpr int Bq = 64, Fq = 256, Tq = 1024, Hq = 1024, Oq = 512;
constexpr int NB_RNN = 128;

// Scratch (allocations forbidden; __device__ globals are the sanctioned path)
__device__ float g_U[(size_t)Bq * Tq * Hq];   // (B, T, H) = x@Wx + b
__device__ float g_S[(size_t)Bq * Tq * Hq];   // (B, T, H) states
__device__ unsigned g_bar;

__global__ void reset_kernel() { g_bar = 0u; }

// ---------------- packed fp32x2 helpers (sm_103a FFMA2 path) ----------------
using u64 = unsigned long long;
__device__ __forceinline__ u64 pack2(float lo, float hi) {
  u64 r; asm("mov.b64 %0, {%1,%2};" : "=l"(r) : "f"(lo), "f"(hi)); return r;
}
__device__ __forceinline__ u64 dup2(float v) { return pack2(v, v); }
__device__ __forceinline__ u64 ffma2(u64 a, u64 b, u64 c) {
  u64 d; asm("fma.rn.f32x2 %0, %1, %2, %3;" : "=l"(d) : "l"(a), "l"(b), "l"(c));
  return d;
}
__device__ __forceinline__ u64 fmul2(u64 a, u64 b) {
  u64 d; asm("mul.rn.f32x2 %0, %1, %2;" : "=l"(d) : "l"(a), "l"(b)); return d;
}
__device__ __forceinline__ u64 fadd2(u64 a, u64 b) {
  u64 d; asm("add.rn.f32x2 %0, %1, %2;" : "=l"(d) : "l"(a), "l"(b)); return d;
}
__device__ __forceinline__ void unpack2(u64 v, float& lo, float& hi) {
  asm("mov.b64 {%0,%1}, %2;" : "=f"(lo), "=f"(hi) : "l"(v));
}

// ---------------------------------------------------------------------------
// Tiled fp32 GEMM with bias: C[M,N] = A*B + bias.  128x128 CTA tile, 8x8
// thread tile (as 8x4 f32x2), K-tile 8.  MODE 0: A[r][f] = x[b,f,t] gather.
// ---------------------------------------------------------------------------
template <int MODE, int KDIM, int NDIM>
__global__ __launch_bounds__(256, 2) void gemm_bias_kernel(
    const float* __restrict__ A, const float* __restrict__ Bm,
    const float* __restrict__ bias, float* __restrict__ C) {
  __shared__ float sA[8][128];
  __shared__ float sB[8][128];
  const int tid = threadIdx.x;
  const int n0 = blockIdx.x * 128;
  const int m0 = blockIdx.y * 128;
  const int tx = tid & 15, ty = tid >> 4;
  const int ia = tid & 127, ja = tid >> 7;

  u64 acc[8][4];
#pragma unroll
  for (int i = 0; i < 8; i++)
#pragma unroll
    for (int p = 0; p < 4; p++) acc[i][p] = 0ull;

  for (int k0 = 0; k0 < KDIM; k0 += 8) {
#pragma unroll
    for (int u = 0; u < 4; u++) {
      const int j = ja + u * 2;
      float v;
      if (MODE == 0) {
        const int r = m0 + ia;
        const int bb = r >> 10;       // T = 1024
        const int tt = r & 1023;
        v = A[(size_t)bb * (Fq * Tq) + (size_t)(k0 + j) * Tq + tt];
      } else {
        v = A[(size_t)(m0 + ia) * KDIM + (k0 + j)];
      }
      sA[j][ia] = v;
      sB[j][ia] = Bm[(size_t)(k0 + j) * NDIM + n0 + ia];
    }
    __syncthreads();
#pragma unroll
    for (int k = 0; k < 8; k++) {
      float a8[8];
      *(float4*)&a8[0] = *(const float4*)&sA[k][ty * 8];
      *(float4*)&a8[4] = *(const float4*)&sA[k][ty * 8 + 4];
      const float4 blo = *(const float4*)&sB[k][tx * 8];
      const float4 bhi = *(const float4*)&sB[k][tx * 8 + 4];
      u64 bp[4];
      bp[0] = pack2(blo.x, blo.y); bp[1] = pack2(blo.z, blo.w);
      bp[2] = pack2(bhi.x, bhi.y); bp[3] = pack2(bhi.z, bhi.w);
#pragma unroll
      for (int i = 0; i < 8; i++) {
        const u64 ai = dup2(a8[i]);
#pragma unroll
        for (int p = 0; p < 4; p++) acc[i][p] = ffma2(ai, bp[p], acc[i][p]);
      }
    }
    __syncthreads();
  }

  float bv[8];
#pragma unroll
  for (int j = 0; j < 8; j++) bv[j] = bias[n0 + tx * 8 + j];
#pragma unroll
  for (int i = 0; i < 8; i++) {
    const size_t row = (size_t)(m0 + ty * 8 + i);
    float c[8];
#pragma unroll
    for (int p = 0; p < 4; p++) unpack2(acc[i][p], c[2 * p], c[2 * p + 1]);
    float4 v0, v1;
    v0.x = c[0] + bv[0]; v0.y = c[1] + bv[1];
    v0.z = c[2] + bv[2]; v0.w = c[3] + bv[3];
    v1.x = c[4] + bv[4]; v1.y = c[5] + bv[5];
    v1.z = c[6] + bv[6]; v1.w = c[7] + bv[7];
    *(float4*)&C[row * NDIM + n0 + tx * 8] = v0;
    *(float4*)&C[row * NDIM + n0 + tx * 8 + 4] = v1;
  }
}

// ---------------------------------------------------------------------------
// Persistent recurrent kernel v2.
// 128 CTAs x 256 threads.  CTA owns columns [j0, j0+8) of the new state.
// Threads split into 2 groups of 128; group g processes b = 2r+g at round r
// (32 rounds).  Thread kt=tid&127 owns k in {kt*4..+3} U {512+kt*4..+3}
// with Wh[k][j0..j0+8) register-stationary as f32x2 pairs (FFMA2 inner
// product: 32 FFMA2/round).  Prefetch depth 2 (4 LDG.128 in flight) hides
// the 262-cyc L2 latency.  Warp partials folded with a 5-stage selective
// shuffle (f32x2 for the wide stages), accumulated into padded SMEM; one
// __syncthreads + combine pass per step.  Grid-wide counter barrier/step.
// ---------------------------------------------------------------------------
__global__ __launch_bounds__(256, 1) void rnn_kernel(const float* __restrict__ Wh) {
  __shared__ float sRed[64][4][9];  // [b][warp-in-group][j] padded, 9.2 KB
  const int tid = threadIdx.x;
  const int lane = tid & 31, warp = tid >> 5;
  const int g = warp >> 2;          // group 0/1
  const int w4 = warp & 3;          // warp within group
  const int j0 = blockIdx.x * 8;
  const int kt = tid & 127;
  const int k1 = kt * 4;            // first k quad
  const int k2 = 512 + kt * 4;      // second k quad

  // Register-stationary Wh: rows k1..k1+3 and k2..k2+3, columns j0..j0+7.
  u64 whA[4][4], whB[4][4];
#pragma unroll
  for (int i = 0; i < 4; i++)
#pragma unroll
    for (int p = 0; p < 4; p++) {
      const float2 a = *(const float2*)&Wh[(size_t)(k1 + i) * Hq + j0 + 2 * p];
      const float2 b = *(const float2*)&Wh[(size_t)(k2 + i) * Hq + j0 + 2 * p];
      whA[i][p] = pack2(a.x, a.y);
      whB[i][p] = pack2(b.x, b.y);
    }

  unsigned target = NB_RNN;
  auto gbarrier = [&]() {
    __syncthreads();
    if (tid == 0) {
      __threadfence();
      atomicAdd(&g_bar, 1u);
      while (*((volatile unsigned*)&g_bar) < target) {}
    }
    __syncthreads();
    target += NB_RNN;
  };

  // t = 0 : S0 = tanh(U0)
#pragma unroll
  for (int u = 0; u < 2; u++) {
    const int idx = tid + u * 256;
    const int b = idx >> 3, j = idx & 7;
    const size_t off = (size_t)b * (Tq * Hq) + j0 + j;
    __stcg(&g_S[off], tanhf(__ldg(&g_U[off])));
  }

  for (int t = 1; t < Tq; t++) {
    gbarrier();  // S[t-1] fully written by all CTAs

    const float* Srow = g_S + (size_t)(t - 1) * Hq;
    auto ldrow = [&](int b, float4& v0, float4& v1) {
      const float* p = Srow + (size_t)b * (Tq * Hq);
      v0 = __ldcg((const float4*)(p + k1));
      v1 = __ldcg((const float4*)(p + k2));
    };

    float4 a0, a1, b0, b1;
    ldrow(g, a0, a1);
    ldrow(2 + g, b0, b1);

#pragma unroll 4
    for (int r = 0; r < 32; r++) {
      const int b = 2 * r + g;
      const float4 c0 = a0, c1 = a1;
      a0 = b0; a1 = b1;
      if (r + 2 < 32) ldrow(2 * (r + 2) + g, b0, b1);

      // inner product: 32 FFMA2 (64 MACs)
      u64 acc[4];
      {
        const u64 s0 = dup2(c0.x);
#pragma unroll
        for (int p = 0; p < 4; p++) acc[p] = fmul2(s0, whA[0][p]);
      }
#pragma unroll
      for (int i = 1; i < 4; i++) {
        const u64 si = dup2(i == 1 ? c0.y : (i == 2 ? c0.z : c0.w));
#pragma unroll
        for (int p = 0; p < 4; p++) acc[p] = ffma2(si, whA[i][p], acc[p]);
      }
#pragma unroll
      for (int i = 0; i < 4; i++) {
        const u64 si = dup2(i == 0 ? c1.x : (i == 1 ? c1.y : (i == 2 ? c1.z : c1.w)));
#pragma unroll
        for (int p = 0; p < 4; p++) acc[p] = ffma2(si, whB[i][p], acc[p]);
      }

      // selective warp fold: after it, lane group (lane>>2) holds j=(lane>>2)&7
      {
        const bool b16 = (lane & 16) != 0;
        u64 s0 = b16 ? acc[0] : acc[2];
        u64 s1 = b16 ? acc[1] : acc[3];
        u64 r0 = __shfl_xor_sync(0xffffffffu, s0, 16);
        u64 r1 = __shfl_xor_sync(0xffffffffu, s1, 16);
        acc[0] = fadd2(b16 ? acc[2] : acc[0], r0);
        acc[1] = fadd2(b16 ? acc[3] : acc[1], r1);
      }
      {
        const bool b8 = (lane & 8) != 0;
        u64 s = b8 ? acc[0] : acc[1];
        u64 rr = __shfl_xor_sync(0xffffffffu, s, 8);
        acc[0] = fadd2(b8 ? acc[1] : acc[0], rr);
      }
      float v;
      {
        float lo, hi;
        unpack2(acc[0], lo, hi);
        const bool b4 = (lane & 4) != 0;
        const float s = b4 ? lo : hi;
        const float rr = __shfl_xor_sync(0xffffffffu, s, 4);
        v = (b4 ? hi : lo) + rr;
      }
      v += __shfl_xor_sync(0xffffffffu, v, 2);
      v += __shfl_xor_sync(0xffffffffu, v, 1);
      if ((lane & 3) == 0) sRed[b][w4][(lane >> 2) & 7] = v;
    }
    __syncthreads();

    // combine 4 warp-partials, add U, tanh, store S[t]
#pragma unroll
    for (int u = 0; u < 2; u++) {
      const int idx = tid + u * 256;
      const int b = idx >> 3, j = idx & 7;
      const float sum = (sRed[b][0][j] + sRed[b][1][j]) +
                        (sRed[b][2][j] + sRed[b][3][j]);
      const size_t off = (size_t)b * (Tq * Hq) + (size_t)t * Hq + j0 + j;
      __stcg(&g_S[off], tanhf(__ldg(&g_U[off]) + sum));
    }
  }
}

extern "C" void kernel_launch(void* const* d_in, const int* in_sizes, int n_in,
                              void* d_out, int out_size) {
  const float* x    = (const float*)d_in[0];
  const float* Wx   = (const float*)d_in[1];
  const float* Wh   = (const float*)d_in[2];
  const float* bv   = (const float*)d_in[3];
  const float* Wout = (const float*)d_in[4];
  const float* bout = (const float*)d_in[5];
  float* out = (float*)d_out;

  float* U = nullptr;
  float* S = nullptr;
  cudaGetSymbolAddress((void**)&U, g_U);
  cudaGetSymbolAddress((void**)&S, g_S);

  reset_kernel<<<1, 1>>>();
  // Phase 1: U = x @ Wx + b   (M = B*T = 65536, K = 256, N = 1024)
  gemm_bias_kernel<0, Fq, Hq><<<dim3(Hq / 128, (Bq * Tq) / 128), 256>>>(x, Wx, bv, U);
  // Phase 2: sequential recurrence, persistent cooperative kernel
  rnn_kernel<<<NB_RNN, 256>>>(Wh);
  // Phase 3: out = states @ Wout + bout  (M = 65536, K = 1024, N = 512)
  gemm_bias_kernel<1, Hq, Oq><<<dim3(Oq / 128, (Bq * Tq) / 128), 256>>>(S, Wout, bout, out);
}

// round 4
// speedup vs baseline: 2.7627x; 1.5678x over previous
#include <cuda_runtime.h>
#include <math.h>

constexpr int Bq = 64, Fq = 256, Tq = 1024, Hq = 1024, Oq = 512;
constexpr int NB_RNN = 128;

// Scratch (allocations forbidden; __device__ globals are the sanctioned path)
__device__ float g_U[(size_t)Bq * Tq * Hq];   // (B, T, H) = x@Wx + b
__device__ float g_S[(size_t)Bq * Tq * Hq];   // (B, T, H) states
__device__ unsigned g_bar;

__global__ void reset_kernel() { g_bar = 0u; }

// ---------------- packed fp32x2 helpers (sm_103a FFMA2 path) ----------------
using u64 = unsigned long long;
__device__ __forceinline__ u64 pack2(float lo, float hi) {
  u64 r; asm("mov.b64 %0, {%1,%2};" : "=l"(r) : "f"(lo), "f"(hi)); return r;
}
__device__ __forceinline__ u64 dup2(float v) { return pack2(v, v); }
__device__ __forceinline__ u64 ffma2(u64 a, u64 b, u64 c) {
  u64 d; asm("fma.rn.f32x2 %0, %1, %2, %3;" : "=l"(d) : "l"(a), "l"(b), "l"(c));
  return d;
}
__device__ __forceinline__ u64 fmul2(u64 a, u64 b) {
  u64 d; asm("mul.rn.f32x2 %0, %1, %2;" : "=l"(d) : "l"(a), "l"(b)); return d;
}
__device__ __forceinline__ u64 fadd2(u64 a, u64 b) {
  u64 d; asm("add.rn.f32x2 %0, %1, %2;" : "=l"(d) : "l"(a), "l"(b)); return d;
}
__device__ __forceinline__ void unpack2(u64 v, float& lo, float& hi) {
  asm("mov.b64 {%0,%1}, %2;" : "=f"(lo), "=f"(hi) : "l"(v));
}

// ---------------------------------------------------------------------------
// Tiled fp32 GEMM with bias: C[M,N] = A*B + bias.  128x128 CTA tile, 8x8
// thread tile (8x4 f32x2), K-tile 8.
// MODE 0: A[r][f] = x[b,f,t] gather (coalesced along t).
// MODE 1: A row-major [M,K]; loaded COALESCED as float4 along K, transposed
//         into sA via STS (fixes the 8x sector-waste column gather).
// ---------------------------------------------------------------------------
template <int MODE, int KDIM, int NDIM>
__global__ __launch_bounds__(256, 2) void gemm_bias_kernel(
    const float* __restrict__ A, const float* __restrict__ Bm,
    const float* __restrict__ bias, float* __restrict__ C) {
  __shared__ float sA[8][128];
  __shared__ float sB[8][128];
  const int tid = threadIdx.x;
  const int n0 = blockIdx.x * 128;
  const int m0 = blockIdx.y * 128;
  const int tx = tid & 15, ty = tid >> 4;
  const int ia = tid & 127, ja = tid >> 7;

  u64 acc[8][4];
#pragma unroll
  for (int i = 0; i < 8; i++)
#pragma unroll
    for (int p = 0; p < 4; p++) acc[i][p] = 0ull;

  for (int k0 = 0; k0 < KDIM; k0 += 8) {
    if (MODE == 0) {
#pragma unroll
      for (int u = 0; u < 4; u++) {
        const int j = ja + u * 2;
        const int r = m0 + ia;
        const int bb = r >> 10;       // T = 1024
        const int tt = r & 1023;
        sA[j][ia] = A[(size_t)bb * (Fq * Tq) + (size_t)(k0 + j) * Tq + tt];
        sB[j][ia] = Bm[(size_t)(k0 + j) * NDIM + n0 + ia];
      }
    } else {
      const int row = tid >> 1;
      const int kk = (tid & 1) * 4;
      const float4 av = *(const float4*)&A[(size_t)(m0 + row) * KDIM + k0 + kk];
      sA[kk + 0][row] = av.x;
      sA[kk + 1][row] = av.y;
      sA[kk + 2][row] = av.z;
      sA[kk + 3][row] = av.w;
#pragma unroll
      for (int u = 0; u < 4; u++) {
        const int j = ja + u * 2;
        sB[j][ia] = Bm[(size_t)(k0 + j) * NDIM + n0 + ia];
      }
    }
    __syncthreads();
#pragma unroll
    for (int k = 0; k < 8; k++) {
      float a8[8];
      *(float4*)&a8[0] = *(const float4*)&sA[k][ty * 8];
      *(float4*)&a8[4] = *(const float4*)&sA[k][ty * 8 + 4];
      const float4 blo = *(const float4*)&sB[k][tx * 8];
      const float4 bhi = *(const float4*)&sB[k][tx * 8 + 4];
      u64 bp[4];
      bp[0] = pack2(blo.x, blo.y); bp[1] = pack2(blo.z, blo.w);
      bp[2] = pack2(bhi.x, bhi.y); bp[3] = pack2(bhi.z, bhi.w);
#pragma unroll
      for (int i = 0; i < 8; i++) {
        const u64 ai = dup2(a8[i]);
#pragma unroll
        for (int p = 0; p < 4; p++) acc[i][p] = ffma2(ai, bp[p], acc[i][p]);
      }
    }
    __syncthreads();
  }

  float bv[8];
#pragma unroll
  for (int j = 0; j < 8; j++) bv[j] = bias[n0 + tx * 8 + j];
#pragma unroll
  for (int i = 0; i < 8; i++) {
    const size_t row = (size_t)(m0 + ty * 8 + i);
    float c[8];
#pragma unroll
    for (int p = 0; p < 4; p++) unpack2(acc[i][p], c[2 * p], c[2 * p + 1]);
    float4 v0, v1;
    v0.x = c[0] + bv[0]; v0.y = c[1] + bv[1];
    v0.z = c[2] + bv[2]; v0.w = c[3] + bv[3];
    v1.x = c[4] + bv[4]; v1.y = c[5] + bv[5];
    v1.z = c[6] + bv[6]; v1.w = c[7] + bv[7];
    *(float4*)&C[row * NDIM + n0 + tx * 8] = v0;
    *(float4*)&C[row * NDIM + n0 + tx * 8 + 4] = v1;
  }
}

// ---------------------------------------------------------------------------
// Persistent recurrent kernel v3.
// 128 CTAs x 512 threads.  CTA owns columns [j0, j0+8).  Threads in 4 groups
// of 128; group g processes b = 4r+g at round r (16 rounds).  Thread kt owns
// k in {kt*4..+3} U {512+kt*4..+3}; Wh register-stationary as f32x2 j-pairs
// PERMUTED by sigma(lane) = (lane>>3)&3: acc[p] accumulates j-pair p^sigma,
// which makes the entire lane fold SEL-FREE:
//   s16: acc[0]+=shfl(acc[2]); acc[1]+=shfl(acc[3])
//   s8 : acc[0]+=shfl(acc[1])
//   s4 : acc[0]+=shfl(acc[0])          (plain halving, same j-pair)
// Lanes with (lane&4)==0 then hold j-pair q=sigma partials over lane bits
// {1,0} -> 16 partials/(b,q) stored to padded SMEM; combine phase reduces
// them, adds preloaded U, applies tanh, stores S[t].  Grid barrier uses
// red.release.gpu + ld.acquire.gpu.
// ---------------------------------------------------------------------------
__global__ __launch_bounds__(512, 1) void rnn_kernel(const float* __restrict__ Wh) {
  __shared__ u64 sRed[64][4][17];   // [b][jpair][16 partials + pad] = 34.8 KB
  const int tid = threadIdx.x;
  const int lane = tid & 31;
  const int g = tid >> 7;           // b-group 0..3
  const int w4 = (tid >> 5) & 3;    // warp within group
  const int j0 = blockIdx.x * 8;
  const int kt = tid & 127;
  const int k1 = kt * 4, k2 = 512 + kt * 4;
  const int sigma = (lane >> 3) & 3;

  // Register-stationary Wh, j-pairs permuted: wh[i][p] holds pair q = p^sigma.
  u64 whA[4][4], whB[4][4];
#pragma unroll
  for (int i = 0; i < 4; i++)
#pragma unroll
    for (int p = 0; p < 4; p++) {
      const int q = p ^ sigma;
      const float2 a = *(const float2*)&Wh[(size_t)(k1 + i) * Hq + j0 + 2 * q];
      const float2 b = *(const float2*)&Wh[(size_t)(k2 + i) * Hq + j0 + 2 * q];
      whA[i][p] = pack2(a.x, a.y);
      whB[i][p] = pack2(b.x, b.y);
    }

  // Output assignment for init / U-preload / combine.
  const int ob = tid >> 3, oj = tid & 7;
  const size_t base_su = (size_t)ob * (Tq * Hq) + j0 + oj;

  unsigned target = NB_RNN;
  u64* barp = (u64*)nullptr; (void)barp;
  auto gbarrier = [&]() {
    __syncthreads();
    if (tid == 0) {
      asm volatile("red.release.gpu.add.u32 [%0], 1;" :: "l"(&g_bar) : "memory");
      unsigned v;
      do {
        asm volatile("ld.acquire.gpu.u32 %0, [%1];" : "=r"(v) : "l"(&g_bar) : "memory");
      } while (v < target);
    }
    __syncthreads();
    target += NB_RNN;
  };

  // t = 0 : S0 = tanh(U0)
  __stcg(&g_S[base_su], tanhf(__ldg(&g_U[base_su])));

  for (int t = 1; t < Tq; t++) {
    // Preload U for this thread's output BEFORE the barrier (independent data)
    const float uval = __ldg(&g_U[base_su + (size_t)t * Hq]);

    gbarrier();  // S[t-1] fully written by all CTAs

    const float* Srow = g_S + (size_t)(t - 1) * Hq;
    auto ldrow = [&](int b, float4& v0, float4& v1) {
      const float* p = Srow + (size_t)b * (Tq * Hq);
      v0 = __ldcg((const float4*)(p + k1));
      v1 = __ldcg((const float4*)(p + k2));
    };

    float4 a0, a1, b0, b1;
    ldrow(g, a0, a1);
    ldrow(4 + g, b0, b1);

#pragma unroll 4
    for (int r = 0; r < 16; r++) {
      const int b = 4 * r + g;
      const float4 c0 = a0, c1 = a1;
      a0 = b0; a1 = b1;
      if (r + 2 < 16) ldrow(4 * (r + 2) + g, b0, b1);

      // inner product: 32 FFMA2 (64 MACs), acc[p] = j-pair p^sigma
      u64 acc[4];
      {
        const u64 s0 = dup2(c0.x);
#pragma unroll
        for (int p = 0; p < 4; p++) acc[p] = fmul2(s0, whA[0][p]);
      }
#pragma unroll
      for (int i = 1; i < 4; i++) {
        const u64 si = dup2(i == 1 ? c0.y : (i == 2 ? c0.z : c0.w));
#pragma unroll
        for (int p = 0; p < 4; p++) acc[p] = ffma2(si, whA[i][p], acc[p]);
      }
#pragma unroll
      for (int i = 0; i < 4; i++) {
        const u64 si = dup2(i == 0 ? c1.x : (i == 1 ? c1.y : (i == 2 ? c1.z : c1.w)));
#pragma unroll
        for (int p = 0; p < 4; p++) acc[p] = ffma2(si, whB[i][p], acc[p]);
      }

      // sel-free sigma-permuted fold
      acc[0] = fadd2(acc[0], __shfl_xor_sync(0xffffffffu, acc[2], 16));
      acc[1] = fadd2(acc[1], __shfl_xor_sync(0xffffffffu, acc[3], 16));
      acc[0] = fadd2(acc[0], __shfl_xor_sync(0xffffffffu, acc[1], 8));
      acc[0] = fadd2(acc[0], __shfl_xor_sync(0xffffffffu, acc[0], 4));
      if ((lane & 4) == 0) sRed[b][sigma][w4 * 4 + (lane & 3)] = acc[0];
    }
    __syncthreads();

    // combine: 1 output/thread: 16 u64 partials -> scalar, +U, tanh, store
    {
      const int q = oj >> 1;
      u64 s0 = fadd2(sRed[ob][q][0], sRed[ob][q][1]);
      u64 s1 = fadd2(sRed[ob][q][2], sRed[ob][q][3]);
      u64 s2 = fadd2(sRed[ob][q][4], sRed[ob][q][5]);
      u64 s3 = fadd2(sRed[ob][q][6], sRed[ob][q][7]);
      u64 s4 = fadd2(sRed[ob][q][8], sRed[ob][q][9]);
      u64 s5 = fadd2(sRed[ob][q][10], sRed[ob][q][11]);
      u64 s6 = fadd2(sRed[ob][q][12], sRed[ob][q][13]);
      u64 s7 = fadd2(sRed[ob][q][14], sRed[ob][q][15]);
      s0 = fadd2(s0, s1); s2 = fadd2(s2, s3);
      s4 = fadd2(s4, s5); s6 = fadd2(s6, s7);
      s0 = fadd2(s0, s2); s4 = fadd2(s4, s6);
      s0 = fadd2(s0, s4);
      float lo, hi;
      unpack2(s0, lo, hi);
      const float dot = (oj & 1) ? hi : lo;
      __stcg(&g_S[base_su + (size_t)t * Hq], tanhf(uval + dot));
    }
  }
}

extern "C" void kernel_launch(void* const* d_in, const int* in_sizes, int n_in,
                              void* d_out, int out_size) {
  const float* x    = (const float*)d_in[0];
  const float* Wx   = (const float*)d_in[1];
  const float* Wh   = (const float*)d_in[2];
  const float* bv   = (const float*)d_in[3];
  const float* Wout = (const float*)d_in[4];
  const float* bout = (const float*)d_in[5];
  float* out = (float*)d_out;

  float* U = nullptr;
  float* S = nullptr;
  cudaGetSymbolAddress((void**)&U, g_U);
  cudaGetSymbolAddress((void**)&S, g_S);

  reset_kernel<<<1, 1>>>();
  // Phase 1: U = x @ Wx + b   (M = B*T = 65536, K = 256, N = 1024)
  gemm_bias_kernel<0, Fq, Hq><<<dim3(Hq / 128, (Bq * Tq) / 128), 256>>>(x, Wx, bv, U);
  // Phase 2: sequential recurrence, persistent cooperative kernel
  rnn_kernel<<<NB_RNN, 512>>>(Wh);
  // Phase 3: out = states @ Wout + bout  (M = 65536, K = 1024, N = 512)
  gemm_bias_kernel<1, Hq, Oq><<<dim3(Oq / 128, (Bq * Tq) / 128), 256>>>(S, Wout, bout, out);
}

// round 6
// speedup vs baseline: 2.8731x; 1.0400x over previous
#include <cuda_runtime.h>
#include <math.h>

constexpr int Bq = 64, Fq = 256, Tq = 1024, Hq = 1024, Oq = 512;
constexpr int NB_RNN = 128;

// Scratch (allocations forbidden; __device__ globals are the sanctioned path)
__device__ float g_U[(size_t)Bq * Tq * Hq];   // (B, T, H) = x@Wx + b
__device__ float g_S[(size_t)Bq * Tq * Hq];   // (B, T, H) states
__device__ unsigned g_bar;

__global__ void reset_kernel() { g_bar = 0u; }

// ---------------- packed fp32x2 helpers (sm_103a FFMA2 path) ----------------
using u64 = unsigned long long;
__device__ __forceinline__ u64 pack2(float lo, float hi) {
  u64 r; asm("mov.b64 %0, {%1,%2};" : "=l"(r) : "f"(lo), "f"(hi)); return r;
}
__device__ __forceinline__ u64 dup2(float v) { return pack2(v, v); }
__device__ __forceinline__ u64 ffma2(u64 a, u64 b, u64 c) {
  u64 d; asm("fma.rn.f32x2 %0, %1, %2, %3;" : "=l"(d) : "l"(a), "l"(b), "l"(c));
  return d;
}
__device__ __forceinline__ u64 fmul2(u64 a, u64 b) {
  u64 d; asm("mul.rn.f32x2 %0, %1, %2;" : "=l"(d) : "l"(a), "l"(b)); return d;
}
__device__ __forceinline__ u64 fadd2(u64 a, u64 b) {
  u64 d; asm("add.rn.f32x2 %0, %1, %2;" : "=l"(d) : "l"(a), "l"(b)); return d;
}
__device__ __forceinline__ void unpack2(u64 v, float& lo, float& hi) {
  asm("mov.b64 {%0,%1}, %2;" : "=f"(lo), "=f"(hi) : "l"(v));
}

// ---------------------------------------------------------------------------
// Tiled fp32 GEMM with bias, DOUBLE-BUFFERED smem (2-stage pipeline, one
// __syncthreads per k-tile; LDG of tile kt+1 overlaps FFMA2 of tile kt).
// 128x128 CTA tile, 8x8 thread tile (8x4 f32x2), K-tile 8.
// MODE 0: A[r][f] = x[b,f,t] gather (coalesced along t).
// MODE 1: A row-major [M,K], loaded coalesced as float4, transposed via STS.
// ---------------------------------------------------------------------------
template <int MODE, int KDIM, int NDIM>
__global__ __launch_bounds__(256, 2) void gemm_bias_kernel(
    const float* __restrict__ A, const float* __restrict__ Bm,
    const float* __restrict__ bias, float* __restrict__ C) {
  __shared__ float sA[2][8][128];
  __shared__ float sB[2][8][128];
  const int tid = threadIdx.x;
  const int n0 = blockIdx.x * 128;
  const int m0 = blockIdx.y * 128;
  const int tx = tid & 15, ty = tid >> 4;
  const int ia = tid & 127, ja = tid >> 7;

  float ra[4], rb[4];
  auto ldg_tile = [&](int k0) {
    if (MODE == 0) {
#pragma unroll
      for (int u = 0; u < 4; u++) {
        const int j = ja + u * 2;
        const int r = m0 + ia;
        const int bb = r >> 10;       // T = 1024
        const int tt = r & 1023;
        ra[u] = A[(size_t)bb * (Fq * Tq) + (size_t)(k0 + j) * Tq + tt];
        rb[u] = Bm[(size_t)(k0 + j) * NDIM + n0 + ia];
      }
    } else {
      const int row = tid >> 1;
      const int kk = (tid & 1) * 4;
      const float4 av = *(const float4*)&A[(size_t)(m0 + row) * KDIM + k0 + kk];
      ra[0] = av.x; ra[1] = av.y; ra[2] = av.z; ra[3] = av.w;
#pragma unroll
      for (int u = 0; u < 4; u++)
        rb[u] = Bm[(size_t)(k0 + ja + u * 2) * NDIM + n0 + ia];
    }
  };
  auto sts_tile = [&](int buf) {
    if (MODE == 0) {
#pragma unroll
      for (int u = 0; u < 4; u++) {
        sA[buf][ja + u * 2][ia] = ra[u];
        sB[buf][ja + u * 2][ia] = rb[u];
      }
    } else {
      const int row = tid >> 1;
      const int kk = (tid & 1) * 4;
#pragma unroll
      for (int i = 0; i < 4; i++) sA[buf][kk + i][row] = ra[i];
#pragma unroll
      for (int u = 0; u < 4; u++) sB[buf][ja + u * 2][ia] = rb[u];
    }
  };

  u64 acc[8][4];
#pragma unroll
  for (int i = 0; i < 8; i++)
#pragma unroll
    for (int p = 0; p < 4; p++) acc[i][p] = 0ull;

  constexpr int KT = KDIM / 8;
  ldg_tile(0);
  sts_tile(0);
  __syncthreads();

  for (int kt = 0; kt < KT; kt++) {
    const int cur = kt & 1;
    if (kt + 1 < KT) ldg_tile((kt + 1) * 8);
#pragma unroll
    for (int k = 0; k < 8; k++) {
      float a8[8];
      *(float4*)&a8[0] = *(const float4*)&sA[cur][k][ty * 8];
      *(float4*)&a8[4] = *(const float4*)&sA[cur][k][ty * 8 + 4];
      const float4 blo = *(const float4*)&sB[cur][k][tx * 8];
      const float4 bhi = *(const float4*)&sB[cur][k][tx * 8 + 4];
      u64 bp[4];
      bp[0] = pack2(blo.x, blo.y); bp[1] = pack2(blo.z, blo.w);
      bp[2] = pack2(bhi.x, bhi.y); bp[3] = pack2(bhi.z, bhi.w);
#pragma unroll
      for (int i = 0; i < 8; i++) {
        const u64 ai = dup2(a8[i]);
#pragma unroll
        for (int p = 0; p < 4; p++) acc[i][p] = ffma2(ai, bp[p], acc[i][p]);
      }
    }
    if (kt + 1 < KT) {
      sts_tile(1 - cur);
      __syncthreads();
    }
  }

  float bv[8];
#pragma unroll
  for (int j = 0; j < 8; j++) bv[j] = bias[n0 + tx * 8 + j];
#pragma unroll
  for (int i = 0; i < 8; i++) {
    const size_t row = (size_t)(m0 + ty * 8 + i);
    float c[8];
#pragma unroll
    for (int p = 0; p < 4; p++) unpack2(acc[i][p], c[2 * p], c[2 * p + 1]);
    float4 v0, v1;
    v0.x = c[0] + bv[0]; v0.y = c[1] + bv[1];
    v0.z = c[2] + bv[2]; v0.w = c[3] + bv[3];
    v1.x = c[4] + bv[4]; v1.y = c[5] + bv[5];
    v1.z = c[6] + bv[6]; v1.w = c[7] + bv[7];
    *(float4*)&C[row * NDIM + n0 + tx * 8] = v0;
    *(float4*)&C[row * NDIM + n0 + tx * 8 + 4] = v1;
  }
}

// ---------------------------------------------------------------------------
// Persistent recurrent kernel v4.
// Same structure as v3 (128 CTAs x 512 thr, sigma-permuted sel-free fold),
// plus:
//  * prefetch ring depth 3 (~768 cyc ahead > loaded L2 latency)
//  * per-CTA staggered b order: b = (4*(r + ctaid%16) + g) & 63, spreading
//    the 128 CTAs' simultaneous reads of S[t-1] across L2 sets.
// ---------------------------------------------------------------------------
__global__ __launch_bounds__(512, 1) void rnn_kernel(const float* __restrict__ Wh) {
  __shared__ u64 sRed[64][4][17];   // [b][jpair][16 partials + pad]
  const int tid = threadIdx.x;
  const int lane = tid & 31;
  const int g = tid >> 7;           // b-group 0..3
  const int w4 = (tid >> 5) & 3;    // warp within group
  const int j0 = blockIdx.x * 8;
  const int kt = tid & 127;
  const int k1 = kt * 4, k2 = 512 + kt * 4;
  const int sigma = (lane >> 3) & 3;
  const int stag = blockIdx.x & 15;

  // Register-stationary Wh, j-pairs permuted: wh[i][p] holds pair q = p^sigma.
  u64 whA[4][4], whB[4][4];
#pragma unroll
  for (int i = 0; i < 4; i++)
#pragma unroll
    for (int p = 0; p < 4; p++) {
      const int q = p ^ sigma;
      const float2 a = *(const float2*)&Wh[(size_t)(k1 + i) * Hq + j0 + 2 * q];
      const float2 b = *(const float2*)&Wh[(size_t)(k2 + i) * Hq + j0 + 2 * q];
      whA[i][p] = pack2(a.x, a.y);
      whB[i][p] = pack2(b.x, b.y);
    }

  // Output assignment for init / U-preload / combine.
  const int ob = tid >> 3, oj = tid & 7;
  const size_t base_su = (size_t)ob * (Tq * Hq) + j0 + oj;

  unsigned target = NB_RNN;
  auto gbarrier = [&]() {
    __syncthreads();
    if (tid == 0) {
      asm volatile("red.release.gpu.add.u32 [%0], 1;" :: "l"(&g_bar) : "memory");
      unsigned v;
      do {
        asm volatile("ld.acquire.gpu.u32 %0, [%1];" : "=r"(v) : "l"(&g_bar) : "memory");
      } while (v < target);
    }
    __syncthreads();
    target += NB_RNN;
  };

  // t = 0 : S0 = tanh(U0)
  __stcg(&g_S[base_su], tanhf(__ldg(&g_U[base_su])));

  for (int t = 1; t < Tq; t++) {
    // Preload U for this thread's output BEFORE the barrier (independent data)
    const float uval = __ldg(&g_U[base_su + (size_t)t * Hq]);

    gbarrier();  // S[t-1] fully written by all CTAs

    const float* Srow = g_S + (size_t)(t - 1) * Hq;
    auto ldrow = [&](int b, float4& v0, float4& v1) {
      const float* p = Srow + (size_t)b * (Tq * Hq);
      v0 = __ldcg((const float4*)(p + k1));
      v1 = __ldcg((const float4*)(p + k2));
    };
    auto bmap = [&](int r) { return (4 * (r + stag) + g) & 63; };

    float4 p0[3], p1[3];
#pragma unroll
    for (int i = 0; i < 3; i++) ldrow(bmap(i), p0[i], p1[i]);

#pragma unroll
    for (int r = 0; r < 16; r++) {
      const int s = r % 3;
      const int b = bmap(r);
      const float4 c0 = p0[s], c1 = p1[s];
      if (r + 3 < 16) ldrow(bmap(r + 3), p0[s], p1[s]);

      // inner product: 32 FFMA2 (64 MACs), acc[p] = j-pair p^sigma
      u64 acc[4];
      {
        const u64 s0 = dup2(c0.x);
#pragma unroll
        for (int p = 0; p < 4; p++) acc[p] = fmul2(s0, whA[0][p]);
      }
#pragma unroll
      for (int i = 1; i < 4; i++) {
        const u64 si = dup2(i == 1 ? c0.y : (i == 2 ? c0.z : c0.w));
#pragma unroll
        for (int p = 0; p < 4; p++) acc[p] = ffma2(si, whA[i][p], acc[p]);
      }
#pragma unroll
      for (int i = 0; i < 4; i++) {
        const u64 si = dup2(i == 0 ? c1.x : (i == 1 ? c1.y : (i == 2 ? c1.z : c1.w)));
#pragma unroll
        for (int p = 0; p < 4; p++) acc[p] = ffma2(si, whB[i][p], acc[p]);
      }

      // sel-free sigma-permuted fold
      acc[0] = fadd2(acc[0], __shfl_xor_sync(0xffffffffu, acc[2], 16));
      acc[1] = fadd2(acc[1], __shfl_xor_sync(0xffffffffu, acc[3], 16));
      acc[0] = fadd2(acc[0], __shfl_xor_sync(0xffffffffu, acc[1], 8));
      acc[0] = fadd2(acc[0], __shfl_xor_sync(0xffffffffu, acc[0], 4));
      if ((lane & 4) == 0) sRed[b][sigma][w4 * 4 + (lane & 3)] = acc[0];
    }
    __syncthreads();

    // combine: 1 output/thread: 16 u64 partials -> scalar, +U, tanh, store
    {
      const int q = oj >> 1;
      u64 s0 = fadd2(sRed[ob][q][0], sRed[ob][q][1]);
      u64 s1 = fadd2(sRed[ob][q][2], sRed[ob][q][3]);
      u64 s2 = fadd2(sRed[ob][q][4], sRed[ob][q][5]);
      u64 s3 = fadd2(sRed[ob][q][6], sRed[ob][q][7]);
      u64 s4 = fadd2(sRed[ob][q][8], sRed[ob][q][9]);
      u64 s5 = fadd2(sRed[ob][q][10], sRed[ob][q][11]);
      u64 s6 = fadd2(sRed[ob][q][12], sRed[ob][q][13]);
      u64 s7 = fadd2(sRed[ob][q][14], sRed[ob][q][15]);
      s0 = fadd2(s0, s1); s2 = fadd2(s2, s3);
      s4 = fadd2(s4, s5); s6 = fadd2(s6, s7);
      s0 = fadd2(s0, s2); s4 = fadd2(s4, s6);
      s0 = fadd2(s0, s4);
      float lo, hi;
      unpack2(s0, lo, hi);
      const float dot = (oj & 1) ? hi : lo;
      __stcg(&g_S[base_su + (size_t)t * Hq], tanhf(uval + dot));
    }
  }
}

extern "C" void kernel_launch(void* const* d_in, const int* in_sizes, int n_in,
                              void* d_out, int out_size) {
  const float* x    = (const float*)d_in[0];
  const float* Wx   = (const float*)d_in[1];
  const float* Wh   = (const float*)d_in[2];
  const float* bv   = (const float*)d_in[3];
  const float* Wout = (const float*)d_in[4];
  const float* bout = (const float*)d_in[5];
  float* out = (float*)d_out;

  float* U = nullptr;
  float* S = nullptr;
  cudaGetSymbolAddress((void**)&U, g_U);
  cudaGetSymbolAddress((void**)&S, g_S);

  reset_kernel<<<1, 1>>>();
  // Phase 1: U = x @ Wx + b   (M = B*T = 65536, K = 256, N = 1024)
  gemm_bias_kernel<0, Fq, Hq><<<dim3(Hq / 128, (Bq * Tq) / 128), 256>>>(x, Wx, bv, U);
  // Phase 2: sequential recurrence, persistent cooperative kernel
  rnn_kernel<<<NB_RNN, 512>>>(Wh);
  // Phase 3: out = states @ Wout + bout  (M = 65536, K = 1024, N = 512)
  gemm_bias_kernel<1, Hq, Oq><<<dim3(Oq / 128, (Bq * Tq) / 128), 256>>>(S, Wout, bout, out);
}